// round 6
// baseline (speedup 1.0000x reference)
#include <cuda_runtime.h>
#include <cuda_bf16.h>
#include <math.h>

#define T_   256
#define B_   64
#define H_   256
#define HID_ 512
#define NTAG 34
#define G4H  1024

__device__ float d_X0[T_*B_*256];
__device__ float d_H1[T_*B_*HID_];
__device__ float d_H2[T_*B_*HID_];
__device__ float d_XP[2u*T_*B_*G4H];
__device__ float d_EM[T_*B_*NTAG];
__device__ float d_hbuf[2*2*H_*B_];   // [dir][pingpong][k][b]
__device__ float d_cbuf[2*H_*B_];     // [dir][k][b]

__global__ void embed_kernel(const int* __restrict__ x, const float* __restrict__ embed) {
    size_t idx = (size_t)blockIdx.x * 256 + threadIdx.x;   // over T*B*64 float4
    int row = (int)(idx >> 6);
    int c   = (int)(idx & 63);
    int tok = x[row];
    ((float4*)d_X0)[idx] = ((const float4*)embed)[(size_t)tok * 64 + c];
}

// C[m,n] = A[m,:].W[n,:] + bi[n] + bh[n];  A: [16384,K], W: [1024,K] per dir (blockIdx.z)
__global__ __launch_bounds__(256, 2)
void sgemm_bias(int asel, const float* __restrict__ Wbase,
                const float* __restrict__ bi_base, const float* __restrict__ bh_base, int K) {
    const float* A = asel ? d_H1 : d_X0;
    const int z = blockIdx.z;
    const float* W  = Wbase + (size_t)z * 1024 * K;
    const float* bi = bi_base + (size_t)z * 1024;
    const float* bh = bh_base + (size_t)z * 1024;
    float* C = d_XP + (size_t)z * (T_*B_*G4H);

    __shared__ float As[8][128];
    __shared__ float Bs[8][128];

    const int tid = threadIdx.x;
    const int m0 = blockIdx.y * 128;
    const int n0 = blockIdx.x * 128;
    const int lrow = tid >> 1;
    const int lk   = (tid & 1) << 2;
    const float* aptr = A + (size_t)(m0 + lrow) * K + lk;
    const float* wptr = W + (size_t)(n0 + lrow) * K + lk;
    const int tx = tid & 15;
    const int ty = tid >> 4;

    float acc[8][8];
#pragma unroll
    for (int i = 0; i < 8; i++)
#pragma unroll
        for (int j = 0; j < 8; j++) acc[i][j] = 0.f;

    for (int kt = 0; kt < (K >> 3); kt++) {
        float4 av = *(const float4*)aptr;
        float4 wv = *(const float4*)wptr;
        aptr += 8; wptr += 8;
        __syncthreads();
        As[lk+0][lrow] = av.x; As[lk+1][lrow] = av.y; As[lk+2][lrow] = av.z; As[lk+3][lrow] = av.w;
        Bs[lk+0][lrow] = wv.x; Bs[lk+1][lrow] = wv.y; Bs[lk+2][lrow] = wv.z; Bs[lk+3][lrow] = wv.w;
        __syncthreads();
#pragma unroll
        for (int kk = 0; kk < 8; kk++) {
            float4 a0 = *(const float4*)&As[kk][ty*8];
            float4 a1 = *(const float4*)&As[kk][ty*8+4];
            float4 b0 = *(const float4*)&Bs[kk][tx*4];
            float4 b1 = *(const float4*)&Bs[kk][64+tx*4];
            float a[8] = {a0.x,a0.y,a0.z,a0.w,a1.x,a1.y,a1.z,a1.w};
            float b[8] = {b0.x,b0.y,b0.z,b0.w,b1.x,b1.y,b1.z,b1.w};
#pragma unroll
            for (int i = 0; i < 8; i++)
#pragma unroll
                for (int j = 0; j < 8; j++) acc[i][j] += a[i]*b[j];
        }
    }
    float bs0[4], bs1[4];
#pragma unroll
    for (int j = 0; j < 4; j++) {
        bs0[j] = bi[n0+tx*4+j] + bh[n0+tx*4+j];
        bs1[j] = bi[n0+64+tx*4+j] + bh[n0+64+tx*4+j];
    }
#pragma unroll
    for (int i = 0; i < 8; i++) {
        float* Crow = C + (size_t)(m0 + ty*8 + i) * 1024;
        *(float4*)(Crow + n0 + tx*4) = make_float4(acc[i][0]+bs0[0], acc[i][1]+bs0[1], acc[i][2]+bs0[2], acc[i][3]+bs0[3]);
        *(float4*)(Crow + n0 + 64 + tx*4) = make_float4(acc[i][4]+bs1[0], acc[i][5]+bs1[1], acc[i][6]+bs1[2], acc[i][7]+bs1[3]);
    }
}

__global__ void zero_state() {
    int i = blockIdx.x * 256 + threadIdx.x;
    if (i < 2*2*H_*B_) d_hbuf[i] = 0.f;
    if (i < 2*H_*B_)   d_cbuf[i] = 0.f;
}

__device__ __forceinline__ float sigf(float v) { return 1.f / (1.f + expf(-v)); }

// One LSTM time step, both directions. 128 CTAs: dir = bx>>6, 4 hidden units/CTA.
__global__ __launch_bounds__(256)
void lstm_step(const float* __restrict__ Whh_base, const int* __restrict__ xtok,
               int ysel, int s) {
    const int tid = threadIdx.x;
    const int bx  = blockIdx.x;
    const int dir = bx >> 6;
    const int u0  = (bx & 63) << 2;
    const int t   = dir ? (T_ - 1 - s) : s;
    const int b   = tid & 63;
    const int u   = tid >> 6;          // 0..3
    const int kh  = u0 + u;
    const int cur = s & 1;

    float* Y = ysel ? d_H2 : d_H1;
    const float* hq     = d_hbuf + (size_t)(dir*2 + cur)     * (H_*B_);
    float*       hn_buf = d_hbuf + (size_t)(dir*2 + (cur^1)) * (H_*B_);
    float*       cq     = d_cbuf + (size_t)dir * (H_*B_);
    const float* Whh    = Whh_base + (size_t)dir * (G4H * H_);

    __shared__ float Wt[256][16];      // [k][g*4+u]
    for (int idx = tid; idx < 4096; idx += 256) {
        int k = idx >> 4, col = idx & 15;
        int g = col >> 2, uu = col & 3;
        Wt[k][col] = Whh[(size_t)(g*256 + u0 + uu) * 256 + k];
    }
    __syncthreads();

    float s0 = 0.f, s1 = 0.f, s2 = 0.f, s3 = 0.f;
#pragma unroll 8
    for (int k = 0; k < 256; k++) {
        float hv = __ldg(hq + k*64 + b);
        s0 += Wt[k][u]      * hv;
        s1 += Wt[k][4 + u]  * hv;
        s2 += Wt[k][8 + u]  * hv;
        s3 += Wt[k][12 + u] * hv;
    }

    const float* xp = d_XP + ((size_t)(dir*T_ + t)*64 + b) * 1024;
    float i_ = sigf(s0 + xp[kh]);
    float f_ = sigf(s1 + xp[256 + kh]);
    float g_ = tanhf(s2 + xp[512 + kh]);
    float o_ = sigf(s3 + xp[768 + kh]);

    float c_old = cq[kh*64 + b];
    float cn = f_*c_old + i_*g_;
    float hnv = o_*tanhf(cn);

    bool m = (xtok[t*64 + b] != 0);
    float h_old = hq[kh*64 + b];
    hn_buf[kh*64 + b] = m ? hnv : h_old;
    cq[kh*64 + b]     = m ? cn : c_old;
    Y[((size_t)t*64 + b)*512 + (dir << 8) + kh] = m ? hnv : 0.f;
}

__global__ void emissions_kernel(const float* __restrict__ w_lin, const float* __restrict__ b_lin) {
    int idx = blockIdx.x * 256 + threadIdx.x;
    if (idx >= T_*B_*NTAG) return;
    int row = idx / NTAG;
    int n   = idx - row * NTAG;
    const float4* hr = (const float4*)(d_H2 + (size_t)row * 512);
    const float4* wr = (const float4*)(w_lin + (size_t)n * 512);
    float acc = 0.f;
#pragma unroll 8
    for (int k = 0; k < 128; k++) {
        float4 h = hr[k]; float4 w = wr[k];
        acc += h.x*w.x + h.y*w.y + h.z*w.z + h.w*w.w;
    }
    d_EM[idx] = acc + b_lin[n];
}

// NOTE: writes tags as FLOAT32 — hypothesis: harness output dtype is float32.
__global__ __launch_bounds__(64)
void viterbi_kernel(const int* __restrict__ x, const float* __restrict__ start,
                    const float* __restrict__ endt, const float* __restrict__ trans,
                    float* __restrict__ out) {
    const int b = blockIdx.x;
    const int tid = threadIdx.x;
    __shared__ float trans_s[NTAG*NTAG];
    __shared__ float score[NTAG];
    __shared__ unsigned char hist[T_-1][NTAG];

    for (int i = tid; i < NTAG*NTAG; i += 64) trans_s[i] = trans[i];
    if (tid < NTAG) score[tid] = start[tid] + d_EM[b*NTAG + tid];
    __syncthreads();

    for (int t = 1; t < T_; t++) {
        float nv = 0.f;
        if (tid < NTAG) {
            float em = d_EM[(t*64 + b)*NTAG + tid];
            float best = -3.402823466e38f;
            int a = 0;
#pragma unroll
            for (int p = 0; p < NTAG; p++) {
                float sv = score[p] + trans_s[p*NTAG + tid];
                if (sv > best) { best = sv; a = p; }
            }
            bool m = (x[t*64 + b] != 0);
            nv = m ? (best + em) : score[tid];
            hist[t-1][tid] = (unsigned char)(m ? a : tid);
        }
        __syncthreads();
        if (tid < NTAG) score[tid] = nv;
        __syncthreads();
    }

    if (tid == 0) {
        float best = -3.402823466e38f;
        int tag = 0;
        for (int n = 0; n < NTAG; n++) {
            float sv = score[n] + endt[n];
            if (sv > best) { best = sv; tag = n; }
        }
        for (int t = T_-1; t >= 1; t--) {
            out[t*64 + b] = (x[t*64 + b] != 0) ? (float)tag : 0.f;
            tag = hist[t-1][tag];
        }
        out[b] = (x[b] != 0) ? (float)tag : 0.f;
    }
}

extern "C" void kernel_launch(void* const* d_in, const int* in_sizes, int n_in,
                              void* d_out, int out_size) {
    // Logical slots (signature order):
    // 0:x 1:sent_lengths 2:embed 3:w_ih_l0 4:w_hh_l0 5:b_ih_l0 6:b_hh_l0
    // 7:w_ih_l1 8:w_hh_l1 9:b_ih_l1 10:b_hh_l1 11:w_lin 12:b_lin
    // 13:start_trans 14:end_trans 15:trans
    const void* P[16];
    if (n_in >= 16 && in_sizes[0] == T_*B_ && in_sizes[2] == 30000*256) {
        for (int i = 0; i < 16; i++) P[i] = d_in[i];
    } else if (n_in >= 15 && in_sizes[0] == T_*B_ && in_sizes[1] == 30000*256) {
        P[0] = d_in[0]; P[1] = d_in[0];
        for (int i = 2; i < 16; i++) P[i] = d_in[i-1];
    } else {
        // sorted-key order fallback
        P[0]  = d_in[15]; P[1]  = d_in[7];  P[2]  = d_in[5];
        P[3]  = d_in[12]; P[4]  = d_in[10]; P[5]  = d_in[2];  P[6]  = d_in[0];
        P[7]  = d_in[13]; P[8]  = d_in[11]; P[9]  = d_in[3];  P[10] = d_in[1];
        P[11] = d_in[14]; P[12] = d_in[4];
        P[13] = d_in[8];  P[14] = d_in[6];  P[15] = d_in[9];
    }

    const int*   x      = (const int*)P[0];
    const float* embed  = (const float*)P[2];
    const float* w_ih0  = (const float*)P[3];
    const float* w_hh0  = (const float*)P[4];
    const float* b_ih0  = (const float*)P[5];
    const float* b_hh0  = (const float*)P[6];
    const float* w_ih1  = (const float*)P[7];
    const float* w_hh1  = (const float*)P[8];
    const float* b_ih1  = (const float*)P[9];
    const float* b_hh1  = (const float*)P[10];
    const float* w_lin  = (const float*)P[11];
    const float* b_lin  = (const float*)P[12];
    const float* startt = (const float*)P[13];
    const float* endt   = (const float*)P[14];
    const float* trans  = (const float*)P[15];
    float* out = (float*)d_out;

    embed_kernel<<<4096, 256>>>(x, embed);
    sgemm_bias<<<dim3(8, 128, 2), 256>>>(0, w_ih0, b_ih0, b_hh0, 256);
    zero_state<<<256, 256>>>();
    for (int s = 0; s < T_; s++) lstm_step<<<128, 256>>>(w_hh0, x, 0, s);
    sgemm_bias<<<dim3(8, 128, 2), 256>>>(1, w_ih1, b_ih1, b_hh1, 512);
    zero_state<<<256, 256>>>();
    for (int s = 0; s < T_; s++) lstm_step<<<128, 256>>>(w_hh1, x, 1, s);
    emissions_kernel<<<(T_*B_*NTAG + 255)/256, 256>>>(w_lin, b_lin);
    viterbi_kernel<<<64, 64>>>(x, startt, endt, trans, out);
}

// round 7
// speedup vs baseline: 1.7486x; 1.7486x over previous
#include <cuda_runtime.h>
#include <cuda_bf16.h>
#include <math.h>

#define T_   256
#define B_   64
#define H_   256
#define HID_ 512
#define NTAG 34
#define G4H  1024

__device__ float d_X0[T_*B_*256];
__device__ float d_H1[T_*B_*HID_];
__device__ float d_H2[T_*B_*HID_];
__device__ float d_XP[2u*T_*B_*G4H];
__device__ float d_EM[T_*B_*NTAG];
__device__ float d_hbuf[2*2*H_*B_];   // [dir][pingpong][k][b]
__device__ unsigned int g_cnt = 0;
__device__ volatile unsigned int g_gen = 0;

__device__ __forceinline__ void grid_barrier(int nblocks) {
    __syncthreads();
    if (threadIdx.x == 0) {
        unsigned gen = g_gen;
        __threadfence();
        if (atomicAdd(&g_cnt, 1u) == (unsigned)(nblocks - 1)) {
            g_cnt = 0;
            __threadfence();
            g_gen = gen + 1;
        } else {
            while (g_gen == gen) { }
        }
        __threadfence();
    }
    __syncthreads();
}

__global__ void embed_kernel(const int* __restrict__ x, const float* __restrict__ embed) {
    size_t idx = (size_t)blockIdx.x * 256 + threadIdx.x;   // over T*B*64 float4
    int row = (int)(idx >> 6);
    int c   = (int)(idx & 63);
    int tok = x[row];
    ((float4*)d_X0)[idx] = ((const float4*)embed)[(size_t)tok * 64 + c];
}

// C[m,n] = A[m,:].W[n,:] + bi[n] + bh[n];  A: [16384,K], W: [1024,K] per dir (blockIdx.z)
__global__ __launch_bounds__(256, 2)
void sgemm_bias(int asel, const float* __restrict__ Wbase,
                const float* __restrict__ bi_base, const float* __restrict__ bh_base, int K) {
    const float* A = asel ? d_H1 : d_X0;
    const int z = blockIdx.z;
    const float* W  = Wbase + (size_t)z * 1024 * K;
    const float* bi = bi_base + (size_t)z * 1024;
    const float* bh = bh_base + (size_t)z * 1024;
    float* C = d_XP + (size_t)z * (T_*B_*G4H);

    __shared__ float As[8][128];
    __shared__ float Bs[8][128];

    const int tid = threadIdx.x;
    const int m0 = blockIdx.y * 128;
    const int n0 = blockIdx.x * 128;
    const int lrow = tid >> 1;
    const int lk   = (tid & 1) << 2;
    const float* aptr = A + (size_t)(m0 + lrow) * K + lk;
    const float* wptr = W + (size_t)(n0 + lrow) * K + lk;
    const int tx = tid & 15;
    const int ty = tid >> 4;

    float acc[8][8];
#pragma unroll
    for (int i = 0; i < 8; i++)
#pragma unroll
        for (int j = 0; j < 8; j++) acc[i][j] = 0.f;

    for (int kt = 0; kt < (K >> 3); kt++) {
        float4 av = *(const float4*)aptr;
        float4 wv = *(const float4*)wptr;
        aptr += 8; wptr += 8;
        __syncthreads();
        As[lk+0][lrow] = av.x; As[lk+1][lrow] = av.y; As[lk+2][lrow] = av.z; As[lk+3][lrow] = av.w;
        Bs[lk+0][lrow] = wv.x; Bs[lk+1][lrow] = wv.y; Bs[lk+2][lrow] = wv.z; Bs[lk+3][lrow] = wv.w;
        __syncthreads();
#pragma unroll
        for (int kk = 0; kk < 8; kk++) {
            float4 a0 = *(const float4*)&As[kk][ty*8];
            float4 a1 = *(const float4*)&As[kk][ty*8+4];
            float4 b0 = *(const float4*)&Bs[kk][tx*4];
            float4 b1 = *(const float4*)&Bs[kk][64+tx*4];
            float a[8] = {a0.x,a0.y,a0.z,a0.w,a1.x,a1.y,a1.z,a1.w};
            float b[8] = {b0.x,b0.y,b0.z,b0.w,b1.x,b1.y,b1.z,b1.w};
#pragma unroll
            for (int i = 0; i < 8; i++)
#pragma unroll
                for (int j = 0; j < 8; j++) acc[i][j] += a[i]*b[j];
        }
    }
    float bs0[4], bs1[4];
#pragma unroll
    for (int j = 0; j < 4; j++) {
        bs0[j] = bi[n0+tx*4+j] + bh[n0+tx*4+j];
        bs1[j] = bi[n0+64+tx*4+j] + bh[n0+64+tx*4+j];
    }
#pragma unroll
    for (int i = 0; i < 8; i++) {
        float* Crow = C + (size_t)(m0 + ty*8 + i) * 1024;
        *(float4*)(Crow + n0 + tx*4) = make_float4(acc[i][0]+bs0[0], acc[i][1]+bs0[1], acc[i][2]+bs0[2], acc[i][3]+bs0[3]);
        *(float4*)(Crow + n0 + 64 + tx*4) = make_float4(acc[i][4]+bs1[0], acc[i][5]+bs1[1], acc[i][6]+bs1[2], acc[i][7]+bs1[3]);
    }
}

__device__ __forceinline__ float sigf(float v) { return 1.f / (1.f + expf(-v)); }

// Persistent scan: 128 CTAs, dir = bx>>6, 4 hidden units per CTA, grid barrier per step.
__global__ __launch_bounds__(256, 1)
void lstm_scan(const float* __restrict__ Whh_base, const int* __restrict__ xtok, int ysel) {
    const int tid = threadIdx.x;
    const int bx  = blockIdx.x;
    const int dir = bx >> 6;
    const int u0  = (bx & 63) << 2;
    float* Y = ysel ? d_H2 : d_H1;
    const float* Whh = Whh_base + (size_t)dir * (G4H * H_);

    __shared__ float Wt[256][16];       // [k][g*4+u]
    __shared__ float Pf[4][16][64];     // [kq][g*4+u][b]

    for (int idx = tid; idx < 4096; idx += 256) {
        int k = idx >> 4, col = idx & 15;
        int g = col >> 2, u = col & 3;
        Wt[k][col] = Whh[(size_t)(g*256 + u0 + u) * 256 + k];
    }

    const int btile = tid & 15;
    const int g     = (tid >> 4) & 3;
    const int kq    = tid >> 6;
    const int eb = tid & 63;
    const int eu = tid >> 6;

    d_hbuf[(size_t)(dir*2 + 0) * (H_*B_) + (u0+eu)*64 + eb] = 0.f;
    float c_reg = 0.f;
    __threadfence();
    grid_barrier(gridDim.x);

    for (int s = 0; s < T_; s++) {
        const int t   = dir ? (T_-1-s) : s;
        const int cur = s & 1;
        const float* hq = d_hbuf + (size_t)(dir*2 + cur) * (H_*B_);
        const float4* h4 = (const float4*)hq;

        float4 ac0 = make_float4(0.f,0.f,0.f,0.f);
        float4 ac1 = ac0, ac2 = ac0, ac3 = ac0;
        const int kbase = kq << 6;
#pragma unroll 8
        for (int kk = 0; kk < 64; kk++) {
            int k = kbase + kk;
            float4 hv = __ldcg(h4 + k*16 + btile);
            float4 wv = *(const float4*)&Wt[k][g << 2];
            ac0.x += wv.x*hv.x; ac0.y += wv.x*hv.y; ac0.z += wv.x*hv.z; ac0.w += wv.x*hv.w;
            ac1.x += wv.y*hv.x; ac1.y += wv.y*hv.y; ac1.z += wv.y*hv.z; ac1.w += wv.y*hv.w;
            ac2.x += wv.z*hv.x; ac2.y += wv.z*hv.y; ac2.z += wv.z*hv.z; ac2.w += wv.z*hv.w;
            ac3.x += wv.w*hv.x; ac3.y += wv.w*hv.y; ac3.z += wv.w*hv.z; ac3.w += wv.w*hv.w;
        }
        *(float4*)&Pf[kq][(g<<2)+0][btile<<2] = ac0;
        *(float4*)&Pf[kq][(g<<2)+1][btile<<2] = ac1;
        *(float4*)&Pf[kq][(g<<2)+2][btile<<2] = ac2;
        *(float4*)&Pf[kq][(g<<2)+3][btile<<2] = ac3;
        __syncthreads();

        const int kh = u0 + eu;
        float s0 = Pf[0][eu][eb]     + Pf[1][eu][eb]     + Pf[2][eu][eb]     + Pf[3][eu][eb];
        float s1 = Pf[0][4+eu][eb]   + Pf[1][4+eu][eb]   + Pf[2][4+eu][eb]   + Pf[3][4+eu][eb];
        float s2 = Pf[0][8+eu][eb]   + Pf[1][8+eu][eb]   + Pf[2][8+eu][eb]   + Pf[3][8+eu][eb];
        float s3 = Pf[0][12+eu][eb]  + Pf[1][12+eu][eb]  + Pf[2][12+eu][eb]  + Pf[3][12+eu][eb];

        const float* xp = d_XP + ((size_t)(dir*T_ + t)*64 + eb) * 1024;
        float i_ = sigf(s0 + xp[kh]);
        float f_ = sigf(s1 + xp[256+kh]);
        float g_ = tanhf(s2 + xp[512+kh]);
        float o_ = sigf(s3 + xp[768+kh]);
        float cn = f_*c_reg + i_*g_;
        float hn = o_*tanhf(cn);

        bool m = (xtok[t*64 + eb] != 0);
        float hold = __ldcg(hq + kh*64 + eb);
        float hw = m ? hn : hold;
        c_reg    = m ? cn : c_reg;

        d_hbuf[(size_t)(dir*2 + (cur^1)) * (H_*B_) + kh*64 + eb] = hw;
        Y[((size_t)t*64 + eb)*512 + (dir<<8) + kh] = m ? hn : 0.f;

        __threadfence();
        grid_barrier(gridDim.x);
    }
}

__global__ void emissions_kernel(const float* __restrict__ w_lin, const float* __restrict__ b_lin) {
    int idx = blockIdx.x * 256 + threadIdx.x;
    if (idx >= T_*B_*NTAG) return;
    int row = idx / NTAG;
    int n   = idx - row * NTAG;
    const float4* hr = (const float4*)(d_H2 + (size_t)row * 512);
    const float4* wr = (const float4*)(w_lin + (size_t)n * 512);
    float acc = 0.f;
#pragma unroll 8
    for (int k = 0; k < 128; k++) {
        float4 h = hr[k]; float4 w = wr[k];
        acc += h.x*w.x + h.y*w.y + h.z*w.z + h.w*w.w;
    }
    d_EM[idx] = acc + b_lin[n];
}

// Output tags as FLOAT32 (harness output dtype is float32 — verified R5).
__global__ __launch_bounds__(64)
void viterbi_kernel(const int* __restrict__ x, const float* __restrict__ start,
                    const float* __restrict__ endt, const float* __restrict__ trans,
                    float* __restrict__ out) {
    const int b = blockIdx.x;
    const int tid = threadIdx.x;
    __shared__ float trans_s[NTAG*NTAG];
    __shared__ float score[NTAG];
    __shared__ unsigned char hist[T_-1][NTAG];

    for (int i = tid; i < NTAG*NTAG; i += 64) trans_s[i] = trans[i];
    if (tid < NTAG) score[tid] = start[tid] + d_EM[b*NTAG + tid];
    __syncthreads();

    for (int t = 1; t < T_; t++) {
        float nv = 0.f;
        if (tid < NTAG) {
            float em = d_EM[(t*64 + b)*NTAG + tid];
            float best = -3.402823466e38f;
            int a = 0;
#pragma unroll
            for (int p = 0; p < NTAG; p++) {
                float sv = score[p] + trans_s[p*NTAG + tid];
                if (sv > best) { best = sv; a = p; }
            }
            bool m = (x[t*64 + b] != 0);
            nv = m ? (best + em) : score[tid];
            hist[t-1][tid] = (unsigned char)(m ? a : tid);
        }
        __syncthreads();
        if (tid < NTAG) score[tid] = nv;
        __syncthreads();
    }

    if (tid == 0) {
        float best = -3.402823466e38f;
        int tag = 0;
        for (int n = 0; n < NTAG; n++) {
            float sv = score[n] + endt[n];
            if (sv > best) { best = sv; tag = n; }
        }
        for (int t = T_-1; t >= 1; t--) {
            out[t*64 + b] = (x[t*64 + b] != 0) ? (float)tag : 0.f;
            tag = hist[t-1][tag];
        }
        out[b] = (x[b] != 0) ? (float)tag : 0.f;
    }
}

extern "C" void kernel_launch(void* const* d_in, const int* in_sizes, int n_in,
                              void* d_out, int out_size) {
    const void* P[16];
    if (n_in >= 16 && in_sizes[0] == T_*B_ && in_sizes[2] == 30000*256) {
        for (int i = 0; i < 16; i++) P[i] = d_in[i];
    } else if (n_in >= 15 && in_sizes[0] == T_*B_ && in_sizes[1] == 30000*256) {
        P[0] = d_in[0]; P[1] = d_in[0];
        for (int i = 2; i < 16; i++) P[i] = d_in[i-1];
    } else {
        P[0]  = d_in[15]; P[1]  = d_in[7];  P[2]  = d_in[5];
        P[3]  = d_in[12]; P[4]  = d_in[10]; P[5]  = d_in[2];  P[6]  = d_in[0];
        P[7]  = d_in[13]; P[8]  = d_in[11]; P[9]  = d_in[3];  P[10] = d_in[1];
        P[11] = d_in[14]; P[12] = d_in[4];
        P[13] = d_in[8];  P[14] = d_in[6];  P[15] = d_in[9];
    }

    const int*   x      = (const int*)P[0];
    const float* embed  = (const float*)P[2];
    const float* w_ih0  = (const float*)P[3];
    const float* w_hh0  = (const float*)P[4];
    const float* b_ih0  = (const float*)P[5];
    const float* b_hh0  = (const float*)P[6];
    const float* w_ih1  = (const float*)P[7];
    const float* w_hh1  = (const float*)P[8];
    const float* b_ih1  = (const float*)P[9];
    const float* b_hh1  = (const float*)P[10];
    const float* w_lin  = (const float*)P[11];
    const float* b_lin  = (const float*)P[12];
    const float* startt = (const float*)P[13];
    const float* endt   = (const float*)P[14];
    const float* trans  = (const float*)P[15];
    float* out = (float*)d_out;

    embed_kernel<<<4096, 256>>>(x, embed);
    sgemm_bias<<<dim3(8, 128, 2), 256>>>(0, w_ih0, b_ih0, b_hh0, 256);
    lstm_scan<<<128, 256>>>(w_hh0, x, 0);
    sgemm_bias<<<dim3(8, 128, 2), 256>>>(1, w_ih1, b_ih1, b_hh1, 512);
    lstm_scan<<<128, 256>>>(w_hh1, x, 1);
    emissions_kernel<<<(T_*B_*NTAG + 255)/256, 256>>>(w_lin, b_lin);
    viterbi_kernel<<<64, 64>>>(x, startt, endt, trans, out);
}

// round 8
// speedup vs baseline: 1.7957x; 1.0269x over previous
#include <cuda_runtime.h>
#include <cuda_bf16.h>
#include <math.h>

#define T_   256
#define B_   64
#define H_   256
#define HID_ 512
#define NTAG 34
#define G4H  1024

__device__ float d_X0[T_*B_*256];
__device__ float d_H1[T_*B_*HID_];
__device__ float d_H2[T_*B_*HID_];
__device__ float d_XP[2u*T_*B_*G4H];
__device__ float d_EM[T_*B_*NTAG];
__device__ float d_hbuf[2*2*H_*B_];   // [dir][pingpong][k][b]
__device__ unsigned int g_cnt = 0;
__device__ volatile unsigned int g_gen = 0;

__device__ __forceinline__ void grid_barrier(int nblocks) {
    __syncthreads();
    if (threadIdx.x == 0) {
        unsigned gen = g_gen;
        __threadfence();
        if (atomicAdd(&g_cnt, 1u) == (unsigned)(nblocks - 1)) {
            g_cnt = 0;
            __threadfence();
            g_gen = gen + 1;
        } else {
            while (g_gen == gen) { }
        }
        __threadfence();
    }
    __syncthreads();
}

__global__ void embed_kernel(const int* __restrict__ x, const float* __restrict__ embed) {
    size_t idx = (size_t)blockIdx.x * 256 + threadIdx.x;   // over T*B*64 float4
    int row = (int)(idx >> 6);
    int c   = (int)(idx & 63);
    int tok = x[row];
    ((float4*)d_X0)[idx] = ((const float4*)embed)[(size_t)tok * 64 + c];
}

// C[m,n] = A[m,:].W[n,:] + bi[n] + bh[n];  A: [16384,K], W: [1024,K] per dir (blockIdx.z)
__global__ __launch_bounds__(256, 2)
void sgemm_bias(int asel, const float* __restrict__ Wbase,
                const float* __restrict__ bi_base, const float* __restrict__ bh_base, int K) {
    const float* A = asel ? d_H1 : d_X0;
    const int z = blockIdx.z;
    const float* W  = Wbase + (size_t)z * 1024 * K;
    const float* bi = bi_base + (size_t)z * 1024;
    const float* bh = bh_base + (size_t)z * 1024;
    float* C = d_XP + (size_t)z * (T_*B_*G4H);

    __shared__ float As[8][128];
    __shared__ float Bs[8][128];

    const int tid = threadIdx.x;
    const int m0 = blockIdx.y * 128;
    const int n0 = blockIdx.x * 128;
    const int lrow = tid >> 1;
    const int lk   = (tid & 1) << 2;
    const float* aptr = A + (size_t)(m0 + lrow) * K + lk;
    const float* wptr = W + (size_t)(n0 + lrow) * K + lk;
    const int tx = tid & 15;
    const int ty = tid >> 4;

    float acc[8][8];
#pragma unroll
    for (int i = 0; i < 8; i++)
#pragma unroll
        for (int j = 0; j < 8; j++) acc[i][j] = 0.f;

    for (int kt = 0; kt < (K >> 3); kt++) {
        float4 av = *(const float4*)aptr;
        float4 wv = *(const float4*)wptr;
        aptr += 8; wptr += 8;
        __syncthreads();
        As[lk+0][lrow] = av.x; As[lk+1][lrow] = av.y; As[lk+2][lrow] = av.z; As[lk+3][lrow] = av.w;
        Bs[lk+0][lrow] = wv.x; Bs[lk+1][lrow] = wv.y; Bs[lk+2][lrow] = wv.z; Bs[lk+3][lrow] = wv.w;
        __syncthreads();
#pragma unroll
        for (int kk = 0; kk < 8; kk++) {
            float4 a0 = *(const float4*)&As[kk][ty*8];
            float4 a1 = *(const float4*)&As[kk][ty*8+4];
            float4 b0 = *(const float4*)&Bs[kk][tx*4];
            float4 b1 = *(const float4*)&Bs[kk][64+tx*4];
            float a[8] = {a0.x,a0.y,a0.z,a0.w,a1.x,a1.y,a1.z,a1.w};
            float b[8] = {b0.x,b0.y,b0.z,b0.w,b1.x,b1.y,b1.z,b1.w};
#pragma unroll
            for (int i = 0; i < 8; i++)
#pragma unroll
                for (int j = 0; j < 8; j++) acc[i][j] += a[i]*b[j];
        }
    }
    float bs0[4], bs1[4];
#pragma unroll
    for (int j = 0; j < 4; j++) {
        bs0[j] = bi[n0+tx*4+j] + bh[n0+tx*4+j];
        bs1[j] = bi[n0+64+tx*4+j] + bh[n0+64+tx*4+j];
    }
#pragma unroll
    for (int i = 0; i < 8; i++) {
        float* Crow = C + (size_t)(m0 + ty*8 + i) * 1024;
        *(float4*)(Crow + n0 + tx*4) = make_float4(acc[i][0]+bs0[0], acc[i][1]+bs0[1], acc[i][2]+bs0[2], acc[i][3]+bs0[3]);
        *(float4*)(Crow + n0 + 64 + tx*4) = make_float4(acc[i][4]+bs1[0], acc[i][5]+bs1[1], acc[i][6]+bs1[2], acc[i][7]+bs1[3]);
    }
}

__device__ __forceinline__ float sigf(float v) { return 1.f / (1.f + expf(-v)); }

// Persistent scan: 128 CTAs, dir = bx>>6, 4 hidden units per CTA, grid barrier per step.
// h staged into smem each step (64 KB) -> inner loop reads smem, not L2.
// Dynamic smem layout (floats): hs[16384] | Wt[4096] | Pf[4096]  = 96 KB
__global__ __launch_bounds__(256, 1)
void lstm_scan(const float* __restrict__ Whh_base, const int* __restrict__ xtok, int ysel) {
    extern __shared__ float sm[];
    float* hs = sm;              // [k][b]        256*64
    float* Wt = sm + 16384;      // [k*16 + g*4+u]
    float* Pf = sm + 20480;      // [kq*1024 + (g*4+u)*64 + b]

    const int tid = threadIdx.x;
    const int bx  = blockIdx.x;
    const int dir = bx >> 6;
    const int u0  = (bx & 63) << 2;
    float* Y = ysel ? d_H2 : d_H1;
    const float* Whh = Whh_base + (size_t)dir * (G4H * H_);

    for (int idx = tid; idx < 4096; idx += 256) {
        int k = idx >> 4, col = idx & 15;
        int g = col >> 2, u = col & 3;
        Wt[k*16 + col] = Whh[(size_t)(g*256 + u0 + u) * 256 + k];
    }

    const int btile = tid & 15;
    const int g     = (tid >> 4) & 3;
    const int kq    = tid >> 6;
    const int eb = tid & 63;
    const int eu = tid >> 6;

    d_hbuf[(size_t)(dir*2 + 0) * (H_*B_) + (u0+eu)*64 + eb] = 0.f;
    float c_reg = 0.f;
    __threadfence();
    grid_barrier(gridDim.x);

    for (int s = 0; s < T_; s++) {
        const int t   = dir ? (T_-1-s) : s;
        const int cur = s & 1;
        const float4* hq4 = (const float4*)(d_hbuf + (size_t)(dir*2 + cur) * (H_*B_));
        float4* hs4 = (float4*)hs;

        // stage h: 4096 float4, 16 per thread, coalesced
#pragma unroll
        for (int i = 0; i < 16; i++)
            hs4[tid + (i << 8)] = __ldcg(&hq4[tid + (i << 8)]);
        __syncthreads();

        float4 ac0 = make_float4(0.f,0.f,0.f,0.f);
        float4 ac1 = ac0, ac2 = ac0, ac3 = ac0;
        const int kbase = kq << 6;
#pragma unroll 8
        for (int kk = 0; kk < 64; kk++) {
            int k = kbase + kk;
            float4 hv = *(const float4*)&hs[(k << 6) + (btile << 2)];
            float4 wv = *(const float4*)&Wt[(k << 4) + (g << 2)];
            ac0.x += wv.x*hv.x; ac0.y += wv.x*hv.y; ac0.z += wv.x*hv.z; ac0.w += wv.x*hv.w;
            ac1.x += wv.y*hv.x; ac1.y += wv.y*hv.y; ac1.z += wv.y*hv.z; ac1.w += wv.y*hv.w;
            ac2.x += wv.z*hv.x; ac2.y += wv.z*hv.y; ac2.z += wv.z*hv.z; ac2.w += wv.z*hv.w;
            ac3.x += wv.w*hv.x; ac3.y += wv.w*hv.y; ac3.z += wv.w*hv.z; ac3.w += wv.w*hv.w;
        }
        const int gu = g << 2;
        *(float4*)&Pf[kq*1024 + (gu+0)*64 + (btile<<2)] = ac0;
        *(float4*)&Pf[kq*1024 + (gu+1)*64 + (btile<<2)] = ac1;
        *(float4*)&Pf[kq*1024 + (gu+2)*64 + (btile<<2)] = ac2;
        *(float4*)&Pf[kq*1024 + (gu+3)*64 + (btile<<2)] = ac3;
        __syncthreads();

        const int kh = u0 + eu;
        float s0 = Pf[eu*64+eb]        + Pf[1024 + eu*64+eb]        + Pf[2048 + eu*64+eb]        + Pf[3072 + eu*64+eb];
        float s1 = Pf[(4+eu)*64+eb]    + Pf[1024 + (4+eu)*64+eb]    + Pf[2048 + (4+eu)*64+eb]    + Pf[3072 + (4+eu)*64+eb];
        float s2 = Pf[(8+eu)*64+eb]    + Pf[1024 + (8+eu)*64+eb]    + Pf[2048 + (8+eu)*64+eb]    + Pf[3072 + (8+eu)*64+eb];
        float s3 = Pf[(12+eu)*64+eb]   + Pf[1024 + (12+eu)*64+eb]   + Pf[2048 + (12+eu)*64+eb]   + Pf[3072 + (12+eu)*64+eb];

        const float* xp = d_XP + ((size_t)(dir*T_ + t)*64 + eb) * 1024;
        float i_ = sigf(s0 + xp[kh]);
        float f_ = sigf(s1 + xp[256+kh]);
        float g_ = tanhf(s2 + xp[512+kh]);
        float o_ = sigf(s3 + xp[768+kh]);
        float cn = f_*c_reg + i_*g_;
        float hn = o_*tanhf(cn);

        bool m = (xtok[t*64 + eb] != 0);
        float hold = hs[(kh << 6) + eb];
        float hw = m ? hn : hold;
        c_reg    = m ? cn : c_reg;

        d_hbuf[(size_t)(dir*2 + (cur^1)) * (H_*B_) + kh*64 + eb] = hw;
        Y[((size_t)t*64 + eb)*512 + (dir<<8) + kh] = m ? hn : 0.f;

        __threadfence();
        grid_barrier(gridDim.x);
    }
}

__global__ void emissions_kernel(const float* __restrict__ w_lin, const float* __restrict__ b_lin) {
    int idx = blockIdx.x * 256 + threadIdx.x;
    if (idx >= T_*B_*NTAG) return;
    int row = idx / NTAG;
    int n   = idx - row * NTAG;
    const float4* hr = (const float4*)(d_H2 + (size_t)row * 512);
    const float4* wr = (const float4*)(w_lin + (size_t)n * 512);
    float acc = 0.f;
#pragma unroll 8
    for (int k = 0; k < 128; k++) {
        float4 h = hr[k]; float4 w = wr[k];
        acc += h.x*w.x + h.y*w.y + h.z*w.z + h.w*w.w;
    }
    d_EM[idx] = acc + b_lin[n];
}

// Output tags as FLOAT32 (harness output dtype is float32 — verified R5).
__global__ __launch_bounds__(64)
void viterbi_kernel(const int* __restrict__ x, const float* __restrict__ start,
                    const float* __restrict__ endt, const float* __restrict__ trans,
                    float* __restrict__ out) {
    const int b = blockIdx.x;
    const int tid = threadIdx.x;
    __shared__ float trans_s[NTAG*NTAG];
    __shared__ float score[NTAG];
    __shared__ unsigned char hist[T_-1][NTAG];

    for (int i = tid; i < NTAG*NTAG; i += 64) trans_s[i] = trans[i];
    if (tid < NTAG) score[tid] = start[tid] + d_EM[b*NTAG + tid];
    __syncthreads();

    for (int t = 1; t < T_; t++) {
        float nv = 0.f;
        if (tid < NTAG) {
            float em = d_EM[(t*64 + b)*NTAG + tid];
            float best = -3.402823466e38f;
            int a = 0;
#pragma unroll
            for (int p = 0; p < NTAG; p++) {
                float sv = score[p] + trans_s[p*NTAG + tid];
                if (sv > best) { best = sv; a = p; }
            }
            bool m = (x[t*64 + b] != 0);
            nv = m ? (best + em) : score[tid];
            hist[t-1][tid] = (unsigned char)(m ? a : tid);
        }
        __syncthreads();
        if (tid < NTAG) score[tid] = nv;
        __syncthreads();
    }

    if (tid == 0) {
        float best = -3.402823466e38f;
        int tag = 0;
        for (int n = 0; n < NTAG; n++) {
            float sv = score[n] + endt[n];
            if (sv > best) { best = sv; tag = n; }
        }
        for (int t = T_-1; t >= 1; t--) {
            out[t*64 + b] = (x[t*64 + b] != 0) ? (float)tag : 0.f;
            tag = hist[t-1][tag];
        }
        out[b] = (x[b] != 0) ? (float)tag : 0.f;
    }
}

extern "C" void kernel_launch(void* const* d_in, const int* in_sizes, int n_in,
                              void* d_out, int out_size) {
    const void* P[16];
    if (n_in >= 16 && in_sizes[0] == T_*B_ && in_sizes[2] == 30000*256) {
        for (int i = 0; i < 16; i++) P[i] = d_in[i];
    } else if (n_in >= 15 && in_sizes[0] == T_*B_ && in_sizes[1] == 30000*256) {
        P[0] = d_in[0]; P[1] = d_in[0];
        for (int i = 2; i < 16; i++) P[i] = d_in[i-1];
    } else {
        P[0]  = d_in[15]; P[1]  = d_in[7];  P[2]  = d_in[5];
        P[3]  = d_in[12]; P[4]  = d_in[10]; P[5]  = d_in[2];  P[6]  = d_in[0];
        P[7]  = d_in[13]; P[8]  = d_in[11]; P[9]  = d_in[3];  P[10] = d_in[1];
        P[11] = d_in[14]; P[12] = d_in[4];
        P[13] = d_in[8];  P[14] = d_in[6];  P[15] = d_in[9];
    }

    const int*   x      = (const int*)P[0];
    const float* embed  = (const float*)P[2];
    const float* w_ih0  = (const float*)P[3];
    const float* w_hh0  = (const float*)P[4];
    const float* b_ih0  = (const float*)P[5];
    const float* b_hh0  = (const float*)P[6];
    const float* w_ih1  = (const float*)P[7];
    const float* w_hh1  = (const float*)P[8];
    const float* b_ih1  = (const float*)P[9];
    const float* b_hh1  = (const float*)P[10];
    const float* w_lin  = (const float*)P[11];
    const float* b_lin  = (const float*)P[12];
    const float* startt = (const float*)P[13];
    const float* endt   = (const float*)P[14];
    const float* trans  = (const float*)P[15];
    float* out = (float*)d_out;

    const int SMEM_SCAN = 96 * 1024;
    cudaFuncSetAttribute(lstm_scan, cudaFuncAttributeMaxDynamicSharedMemorySize, SMEM_SCAN);

    embed_kernel<<<4096, 256>>>(x, embed);
    sgemm_bias<<<dim3(8, 128, 2), 256>>>(0, w_ih0, b_ih0, b_hh0, 256);
    lstm_scan<<<128, 256, SMEM_SCAN>>>(w_hh0, x, 0);
    sgemm_bias<<<dim3(8, 128, 2), 256>>>(1, w_ih1, b_ih1, b_hh1, 512);
    lstm_scan<<<128, 256, SMEM_SCAN>>>(w_hh1, x, 1);
    emissions_kernel<<<(T_*B_*NTAG + 255)/256, 256>>>(w_lin, b_lin);
    viterbi_kernel<<<64, 64>>>(x, startt, endt, trans, out);
}

// round 9
// speedup vs baseline: 2.0384x; 1.1352x over previous
#include <cuda_runtime.h>
#include <cuda_bf16.h>
#include <math.h>

#define T_   256
#define B_   64
#define H_   256
#define HID_ 512
#define NTAG 34
#define G4H  1024

__device__ float d_X0[T_*B_*256];
__device__ float d_H1[T_*B_*HID_];
__device__ float d_H2[T_*B_*HID_];
__device__ float d_XP[2u*T_*B_*G4H];   // layout: [dir][t][gate n (1024)][b (64)]
__device__ float d_EM[T_*B_*NTAG];
__device__ float d_hbuf[2*2*H_*B_];    // [dir][pingpong][k][b]
__device__ unsigned int g_cnt = 0;
__device__ volatile unsigned int g_gen = 0;

// packed dual fp32 FMA (exact fp32 per lane)
#define FMA2(d, a, b) asm("fma.rn.f32x2 %0, %1, %2, %0;" : "+l"(d) : "l"(a), "l"(b))

__device__ __forceinline__ float2 u64_as_f2(unsigned long long v) {
    float2 r; asm("mov.b64 {%0, %1}, %2;" : "=f"(r.x), "=f"(r.y) : "l"(v)); return r;
}

// Grid barrier: fences only on thread 0 (cumulative via __syncthreads).
__device__ __forceinline__ void grid_barrier(int nblocks) {
    __syncthreads();
    if (threadIdx.x == 0) {
        unsigned gen = g_gen;
        __threadfence();
        if (atomicAdd(&g_cnt, 1u) == (unsigned)(nblocks - 1)) {
            g_cnt = 0;
            __threadfence();
            g_gen = gen + 1;
        } else {
            while (g_gen == gen) { }
        }
        __threadfence();
    }
    __syncthreads();
}

__global__ void embed_kernel(const int* __restrict__ x, const float* __restrict__ embed) {
    size_t idx = (size_t)blockIdx.x * 256 + threadIdx.x;   // over T*B*64 float4
    int row = (int)(idx >> 6);
    int c   = (int)(idx & 63);
    int tok = x[row];
    ((float4*)d_X0)[idx] = ((const float4*)embed)[(size_t)tok * 64 + c];
}

// C[dir][t][n][b] = A[m=t*64+b,:].W[n,:] + bi[n] + bh[n]
// A: [16384,K], W: [1024,K] per dir (blockIdx.z). f32x2 inner loop.
__global__ __launch_bounds__(256, 2)
void sgemm_bias(int asel, const float* __restrict__ Wbase,
                const float* __restrict__ bi_base, const float* __restrict__ bh_base, int K) {
    const float* A = asel ? d_H1 : d_X0;
    const int z = blockIdx.z;
    const float* W  = Wbase + (size_t)z * 1024 * K;
    const float* bi = bi_base + (size_t)z * 1024;
    const float* bh = bh_base + (size_t)z * 1024;
    float* C = d_XP + (size_t)z * (T_*B_*G4H);

    __shared__ float2 As2[8][128];   // duplicated-pair A values
    __shared__ float  Bs[8][128];

    const int tid = threadIdx.x;
    const int m0 = blockIdx.y * 128;
    const int n0 = blockIdx.x * 128;
    const int lrow = tid >> 1;
    const int lk   = (tid & 1) << 2;
    const float* aptr = A + (size_t)(m0 + lrow) * K + lk;
    const float* wptr = W + (size_t)(n0 + lrow) * K + lk;
    const int tx = tid & 15;
    const int ty = tid >> 4;

    unsigned long long acc2[8][4];
#pragma unroll
    for (int i = 0; i < 8; i++)
#pragma unroll
        for (int j = 0; j < 4; j++) acc2[i][j] = 0ULL;

    for (int kt = 0; kt < (K >> 3); kt++) {
        float4 av = *(const float4*)aptr;
        float4 wv = *(const float4*)wptr;
        aptr += 8; wptr += 8;
        __syncthreads();
        As2[lk+0][lrow] = make_float2(av.x, av.x);
        As2[lk+1][lrow] = make_float2(av.y, av.y);
        As2[lk+2][lrow] = make_float2(av.z, av.z);
        As2[lk+3][lrow] = make_float2(av.w, av.w);
        Bs[lk+0][lrow] = wv.x; Bs[lk+1][lrow] = wv.y; Bs[lk+2][lrow] = wv.z; Bs[lk+3][lrow] = wv.w;
        __syncthreads();
#pragma unroll
        for (int kk = 0; kk < 8; kk++) {
            ulonglong2 b0 = *(const ulonglong2*)&Bs[kk][tx*4];
            ulonglong2 b1 = *(const ulonglong2*)&Bs[kk][64 + tx*4];
            ulonglong2 a01 = *(const ulonglong2*)&As2[kk][ty*8];
            ulonglong2 a23 = *(const ulonglong2*)&As2[kk][ty*8+2];
            ulonglong2 a45 = *(const ulonglong2*)&As2[kk][ty*8+4];
            ulonglong2 a67 = *(const ulonglong2*)&As2[kk][ty*8+6];
            unsigned long long aD[8] = {a01.x,a01.y,a23.x,a23.y,a45.x,a45.y,a67.x,a67.y};
#pragma unroll
            for (int i = 0; i < 8; i++) {
                FMA2(acc2[i][0], aD[i], b0.x);
                FMA2(acc2[i][1], aD[i], b0.y);
                FMA2(acc2[i][2], aD[i], b1.x);
                FMA2(acc2[i][3], aD[i], b1.y);
            }
        }
    }
    float bs0[4], bs1[4];
#pragma unroll
    for (int j = 0; j < 4; j++) {
        bs0[j] = bi[n0+tx*4+j] + bh[n0+tx*4+j];
        bs1[j] = bi[n0+64+tx*4+j] + bh[n0+64+tx*4+j];
    }
#pragma unroll
    for (int i = 0; i < 8; i++) {
        int m  = m0 + ty*8 + i;
        int tt = m >> 6;
        int bb = m & 63;
        float* Cb = C + (size_t)tt * (G4H*64) + bb;
        float2 v0 = u64_as_f2(acc2[i][0]);
        float2 v1 = u64_as_f2(acc2[i][1]);
        float2 v2 = u64_as_f2(acc2[i][2]);
        float2 v3 = u64_as_f2(acc2[i][3]);
        Cb[(size_t)(n0+tx*4+0)*64]    = v0.x + bs0[0];
        Cb[(size_t)(n0+tx*4+1)*64]    = v0.y + bs0[1];
        Cb[(size_t)(n0+tx*4+2)*64]    = v1.x + bs0[2];
        Cb[(size_t)(n0+tx*4+3)*64]    = v1.y + bs0[3];
        Cb[(size_t)(n0+64+tx*4+0)*64] = v2.x + bs1[0];
        Cb[(size_t)(n0+64+tx*4+1)*64] = v2.y + bs1[1];
        Cb[(size_t)(n0+64+tx*4+2)*64] = v3.x + bs1[2];
        Cb[(size_t)(n0+64+tx*4+3)*64] = v3.y + bs1[3];
    }
}

__device__ __forceinline__ float sigf(float v) { return 1.f / (1.f + expf(-v)); }

// Persistent scan: 128 CTAs, dir = bx>>6, 4 hidden units per CTA, grid barrier per step.
// smem (floats): hs[16384] | Wt2[4096 float2 = 8192 floats] | Pf[4096]  = 112 KB
__global__ __launch_bounds__(256, 1)
void lstm_scan(const float* __restrict__ Whh_base, const int* __restrict__ xtok, int ysel) {
    extern __shared__ float sm[];
    float*  hs  = sm;                          // [k][b] 256*64
    float2* Wt2 = (float2*)(sm + 16384);       // [k*16 + g*4+u] duplicated pairs
    float*  Pf  = sm + 16384 + 8192;           // [kq*1024 + (g*4+u)*64 + b]

    const int tid = threadIdx.x;
    const int dir = blockIdx.x >> 6;
    const int u0  = (blockIdx.x & 63) << 2;
    float* Y = ysel ? d_H2 : d_H1;
    const float* Whh = Whh_base + (size_t)dir * (G4H * H_);

    for (int idx = tid; idx < 4096; idx += 256) {
        int k = idx >> 4, col = idx & 15;
        int g = col >> 2, u = col & 3;
        float w = Whh[(size_t)(g*256 + u0 + u) * 256 + k];
        Wt2[k*16 + col] = make_float2(w, w);
    }

    const int btile = tid & 15;
    const int g     = (tid >> 4) & 3;
    const int kq    = tid >> 6;
    const int eb    = tid & 63;
    const int eu    = tid >> 6;
    const int kh    = u0 + eu;

    d_hbuf[(size_t)(dir*2 + 0) * (H_*B_) + kh*64 + eb] = 0.f;
    float c_reg = 0.f;
    grid_barrier(gridDim.x);

    for (int s = 0; s < T_; s++) {
        const int t   = dir ? (T_-1-s) : s;
        const int cur = s & 1;
        const float4* hq4 = (const float4*)(d_hbuf + (size_t)(dir*2 + cur) * (H_*B_));
        float4* hs4 = (float4*)hs;

        // stage h: 4096 float4, 16 per thread, coalesced
#pragma unroll
        for (int i = 0; i < 16; i++)
            hs4[tid + (i << 8)] = __ldcg(&hq4[tid + (i << 8)]);

        // prefetch xp (coalesced, transposed layout) + token; consumed after compute
        const float* xpt = d_XP + (size_t)(dir*T_ + t) * (G4H*64);
        float xp0 = __ldcg(xpt + (size_t)(0*256 + kh)*64 + eb);
        float xp1 = __ldcg(xpt + (size_t)(1*256 + kh)*64 + eb);
        float xp2 = __ldcg(xpt + (size_t)(2*256 + kh)*64 + eb);
        float xp3 = __ldcg(xpt + (size_t)(3*256 + kh)*64 + eb);
        int   tok = __ldg(&xtok[t*64 + eb]);
        __syncthreads();

        unsigned long long acc[8];
#pragma unroll
        for (int i = 0; i < 8; i++) acc[i] = 0ULL;
        const int kbase = kq << 6;
#pragma unroll 8
        for (int kk = 0; kk < 64; kk++) {
            int k = kbase + kk;
            ulonglong2 hp = *(const ulonglong2*)&hs[(k << 6) + (btile << 2)];
            ulonglong2 wa = *(const ulonglong2*)&Wt2[k*16 + (g << 2)];
            ulonglong2 wb = *(const ulonglong2*)&Wt2[k*16 + (g << 2) + 2];
            FMA2(acc[0], wa.x, hp.x); FMA2(acc[1], wa.x, hp.y);
            FMA2(acc[2], wa.y, hp.x); FMA2(acc[3], wa.y, hp.y);
            FMA2(acc[4], wb.x, hp.x); FMA2(acc[5], wb.x, hp.y);
            FMA2(acc[6], wb.y, hp.x); FMA2(acc[7], wb.y, hp.y);
        }
        float hold = hs[(kh << 6) + eb];
#pragma unroll
        for (int u = 0; u < 4; u++) {
            float2 p0 = u64_as_f2(acc[u*2 + 0]);
            float2 p1 = u64_as_f2(acc[u*2 + 1]);
            *(float4*)&Pf[kq*1024 + ((g << 2) + u)*64 + (btile << 2)] =
                make_float4(p0.x, p0.y, p1.x, p1.y);
        }
        __syncthreads();

        float s0 = Pf[eu*64+eb]      + Pf[1024 + eu*64+eb]      + Pf[2048 + eu*64+eb]      + Pf[3072 + eu*64+eb];
        float s1 = Pf[(4+eu)*64+eb]  + Pf[1024 + (4+eu)*64+eb]  + Pf[2048 + (4+eu)*64+eb]  + Pf[3072 + (4+eu)*64+eb];
        float s2 = Pf[(8+eu)*64+eb]  + Pf[1024 + (8+eu)*64+eb]  + Pf[2048 + (8+eu)*64+eb]  + Pf[3072 + (8+eu)*64+eb];
        float s3 = Pf[(12+eu)*64+eb] + Pf[1024 + (12+eu)*64+eb] + Pf[2048 + (12+eu)*64+eb] + Pf[3072 + (12+eu)*64+eb];

        float i_ = sigf(s0 + xp0);
        float f_ = sigf(s1 + xp1);
        float g_ = tanhf(s2 + xp2);
        float o_ = sigf(s3 + xp3);
        float cn = f_*c_reg + i_*g_;
        float hn = o_*tanhf(cn);

        bool m = (tok != 0);
        float hw = m ? hn : hold;
        c_reg    = m ? cn : c_reg;

        d_hbuf[(size_t)(dir*2 + (cur^1)) * (H_*B_) + kh*64 + eb] = hw;
        Y[((size_t)t*64 + eb)*512 + (dir << 8) + kh] = m ? hn : 0.f;

        grid_barrier(gridDim.x);
    }
}

__global__ void emissions_kernel(const float* __restrict__ w_lin, const float* __restrict__ b_lin) {
    int idx = blockIdx.x * 256 + threadIdx.x;
    if (idx >= T_*B_*NTAG) return;
    int row = idx / NTAG;
    int n   = idx - row * NTAG;
    const float4* hr = (const float4*)(d_H2 + (size_t)row * 512);
    const float4* wr = (const float4*)(w_lin + (size_t)n * 512);
    float acc = 0.f;
#pragma unroll 8
    for (int k = 0; k < 128; k++) {
        float4 h = hr[k]; float4 w = wr[k];
        acc += h.x*w.x + h.y*w.y + h.z*w.z + h.w*w.w;
    }
    d_EM[idx] = acc + b_lin[n];
}

// Output tags as FLOAT32 (harness output dtype is float32 — verified R5).
__global__ __launch_bounds__(64)
void viterbi_kernel(const int* __restrict__ x, const float* __restrict__ start,
                    const float* __restrict__ endt, const float* __restrict__ trans,
                    float* __restrict__ out) {
    const int b = blockIdx.x;
    const int tid = threadIdx.x;
    __shared__ float trans_s[NTAG*NTAG];
    __shared__ float score[NTAG];
    __shared__ unsigned char hist[T_-1][NTAG];

    for (int i = tid; i < NTAG*NTAG; i += 64) trans_s[i] = trans[i];
    if (tid < NTAG) score[tid] = start[tid] + d_EM[b*NTAG + tid];
    __syncthreads();

    for (int t = 1; t < T_; t++) {
        float nv = 0.f;
        if (tid < NTAG) {
            float em = d_EM[(t*64 + b)*NTAG + tid];
            float best = -3.402823466e38f;
            int a = 0;
#pragma unroll
            for (int p = 0; p < NTAG; p++) {
                float sv = score[p] + trans_s[p*NTAG + tid];
                if (sv > best) { best = sv; a = p; }
            }
            bool m = (x[t*64 + b] != 0);
            nv = m ? (best + em) : score[tid];
            hist[t-1][tid] = (unsigned char)(m ? a : tid);
        }
        __syncthreads();
        if (tid < NTAG) score[tid] = nv;
        __syncthreads();
    }

    if (tid == 0) {
        float best = -3.402823466e38f;
        int tag = 0;
        for (int n = 0; n < NTAG; n++) {
            float sv = score[n] + endt[n];
            if (sv > best) { best = sv; tag = n; }
        }
        for (int t = T_-1; t >= 1; t--) {
            out[t*64 + b] = (x[t*64 + b] != 0) ? (float)tag : 0.f;
            tag = hist[t-1][tag];
        }
        out[b] = (x[b] != 0) ? (float)tag : 0.f;
    }
}

extern "C" void kernel_launch(void* const* d_in, const int* in_sizes, int n_in,
                              void* d_out, int out_size) {
    const void* P[16];
    if (n_in >= 16 && in_sizes[0] == T_*B_ && in_sizes[2] == 30000*256) {
        for (int i = 0; i < 16; i++) P[i] = d_in[i];
    } else if (n_in >= 15 && in_sizes[0] == T_*B_ && in_sizes[1] == 30000*256) {
        P[0] = d_in[0]; P[1] = d_in[0];
        for (int i = 2; i < 16; i++) P[i] = d_in[i-1];
    } else {
        P[0]  = d_in[15]; P[1]  = d_in[7];  P[2]  = d_in[5];
        P[3]  = d_in[12]; P[4]  = d_in[10]; P[5]  = d_in[2];  P[6]  = d_in[0];
        P[7]  = d_in[13]; P[8]  = d_in[11]; P[9]  = d_in[3];  P[10] = d_in[1];
        P[11] = d_in[14]; P[12] = d_in[4];
        P[13] = d_in[8];  P[14] = d_in[6];  P[15] = d_in[9];
    }

    const int*   x      = (const int*)P[0];
    const float* embed  = (const float*)P[2];
    const float* w_ih0  = (const float*)P[3];
    const float* w_hh0  = (const float*)P[4];
    const float* b_ih0  = (const float*)P[5];
    const float* b_hh0  = (const float*)P[6];
    const float* w_ih1  = (const float*)P[7];
    const float* w_hh1  = (const float*)P[8];
    const float* b_ih1  = (const float*)P[9];
    const float* b_hh1  = (const float*)P[10];
    const float* w_lin  = (const float*)P[11];
    const float* b_lin  = (const float*)P[12];
    const float* startt = (const float*)P[13];
    const float* endt   = (const float*)P[14];
    const float* trans  = (const float*)P[15];
    float* out = (float*)d_out;

    const int SMEM_SCAN = 112 * 1024;
    cudaFuncSetAttribute(lstm_scan, cudaFuncAttributeMaxDynamicSharedMemorySize, SMEM_SCAN);

    embed_kernel<<<4096, 256>>>(x, embed);
    sgemm_bias<<<dim3(8, 128, 2), 256>>>(0, w_ih0, b_ih0, b_hh0, 256);
    lstm_scan<<<128, 256, SMEM_SCAN>>>(w_hh0, x, 0);
    sgemm_bias<<<dim3(8, 128, 2), 256>>>(1, w_ih1, b_ih1, b_hh1, 512);
    lstm_scan<<<128, 256, SMEM_SCAN>>>(w_hh1, x, 1);
    emissions_kernel<<<(T_*B_*NTAG + 255)/256, 256>>>(w_lin, b_lin);
    viterbi_kernel<<<64, 64>>>(x, startt, endt, trans, out);
}

// round 10
// speedup vs baseline: 2.1848x; 1.0718x over previous
#include <cuda_runtime.h>
#include <cuda_bf16.h>
#include <math.h>

#define T_   256
#define B_   64
#define H_   256
#define HID_ 512
#define NTAG 34
#define G4H  1024

__device__ float d_X0[T_*B_*256];
__device__ float d_H1[T_*B_*HID_];
__device__ float d_H2[T_*B_*HID_];
__device__ float d_XP[2u*T_*B_*G4H];   // layout: [dir][t][gate n (1024)][b (64)]
__device__ float d_EM[T_*B_*NTAG];
__device__ float d_hbuf[2*2*H_*B_];    // [dir][pingpong][k][b]
__device__ unsigned int g_cnt2[2] = {0, 0};
__device__ volatile unsigned int g_gen2[2] = {0, 0};

// packed dual fp32 FMA (exact fp32 per lane)
#define FMA2(d, a, b) asm("fma.rn.f32x2 %0, %1, %2, %0;" : "+l"(d) : "l"(a), "l"(b))

__device__ __forceinline__ float2 u64_as_f2(unsigned long long v) {
    float2 r; asm("mov.b64 {%0, %1}, %2;" : "=f"(r.x), "=f"(r.y) : "l"(v)); return r;
}

// Per-direction grid barrier (64 CTAs each); fences only on thread 0.
__device__ __forceinline__ void grid_barrier_dir(int dir, int nblocks) {
    __syncthreads();
    if (threadIdx.x == 0) {
        unsigned gen = g_gen2[dir];
        __threadfence();
        if (atomicAdd(&g_cnt2[dir], 1u) == (unsigned)(nblocks - 1)) {
            g_cnt2[dir] = 0;
            __threadfence();
            g_gen2[dir] = gen + 1;
        } else {
            while (g_gen2[dir] == gen) { }
        }
        __threadfence();
    }
    __syncthreads();
}

__global__ void embed_kernel(const int* __restrict__ x, const float* __restrict__ embed) {
    size_t idx = (size_t)blockIdx.x * 256 + threadIdx.x;   // over T*B*64 float4
    int row = (int)(idx >> 6);
    int c   = (int)(idx & 63);
    int tok = x[row];
    ((float4*)d_X0)[idx] = ((const float4*)embed)[(size_t)tok * 64 + c];
}

// Transposed output: C[t][n][b] = A[m=t*64+b,:].W[n,:] + bi[n] + bh[n]
// A: [16384,K], W: [1024,K] per dir (blockIdx.z). Scalar FFMA inner (R7-proven).
__global__ __launch_bounds__(256, 2)
void sgemm_bias(int asel, const float* __restrict__ Wbase,
                const float* __restrict__ bi_base, const float* __restrict__ bh_base, int K) {
    const float* A = asel ? d_H1 : d_X0;
    const int z = blockIdx.z;
    const float* W  = Wbase + (size_t)z * 1024 * K;
    const float* bi = bi_base + (size_t)z * 1024;
    const float* bh = bh_base + (size_t)z * 1024;
    float* C = d_XP + (size_t)z * (T_*B_*G4H);

    __shared__ float As[8][128];
    __shared__ float Bs[8][128];

    const int tid = threadIdx.x;
    const int m0 = blockIdx.y * 128;
    const int n0 = blockIdx.x * 128;
    const int lrow = tid >> 1;
    const int lk   = (tid & 1) << 2;
    const float* aptr = A + (size_t)(m0 + lrow) * K + lk;
    const float* wptr = W + (size_t)(n0 + lrow) * K + lk;
    const int tx = tid & 15;
    const int ty = tid >> 4;

    float acc[8][8];
#pragma unroll
    for (int i = 0; i < 8; i++)
#pragma unroll
        for (int j = 0; j < 8; j++) acc[i][j] = 0.f;

    for (int kt = 0; kt < (K >> 3); kt++) {
        float4 av = *(const float4*)aptr;
        float4 wv = *(const float4*)wptr;
        aptr += 8; wptr += 8;
        __syncthreads();
        As[lk+0][lrow] = av.x; As[lk+1][lrow] = av.y; As[lk+2][lrow] = av.z; As[lk+3][lrow] = av.w;
        Bs[lk+0][lrow] = wv.x; Bs[lk+1][lrow] = wv.y; Bs[lk+2][lrow] = wv.z; Bs[lk+3][lrow] = wv.w;
        __syncthreads();
#pragma unroll
        for (int kk = 0; kk < 8; kk++) {
            float4 a0 = *(const float4*)&As[kk][ty*8];
            float4 a1 = *(const float4*)&As[kk][ty*8+4];
            float4 b0 = *(const float4*)&Bs[kk][tx*4];
            float4 b1 = *(const float4*)&Bs[kk][64+tx*4];
            float a[8] = {a0.x,a0.y,a0.z,a0.w,a1.x,a1.y,a1.z,a1.w};
            float b[8] = {b0.x,b0.y,b0.z,b0.w,b1.x,b1.y,b1.z,b1.w};
#pragma unroll
            for (int i = 0; i < 8; i++)
#pragma unroll
                for (int j = 0; j < 8; j++) acc[i][j] += a[i]*b[j];
        }
    }
    // transposed epilogue: float4 over m/b axis (i contiguous in m => b)
    // thread covers m = m0 + ty*8 + i  ->  t = m>>6, b = m&63
    const int tt = (m0 >> 6) + (ty >> 3);        // ty 0..7 -> t0, ty 8..15 -> t0+1
    const int b0 = (ty & 7) * 8;
    float* Ct = C + (size_t)tt * (G4H*64);
#pragma unroll
    for (int j = 0; j < 8; j++) {
        int n = (j < 4) ? (n0 + tx*4 + j) : (n0 + 64 + tx*4 + (j - 4));
        float bias = bi[n] + bh[n];
        *(float4*)(Ct + (size_t)n*64 + b0) =
            make_float4(acc[0][j]+bias, acc[1][j]+bias, acc[2][j]+bias, acc[3][j]+bias);
        *(float4*)(Ct + (size_t)n*64 + b0 + 4) =
            make_float4(acc[4][j]+bias, acc[5][j]+bias, acc[6][j]+bias, acc[7][j]+bias);
    }
}

__device__ __forceinline__ float sigf(float v) { return 1.f / (1.f + expf(-v)); }

// Persistent scan: 128 CTAs, dir = bx>>6, 4 hidden units per CTA.
// Per-direction barrier (64 CTAs) each step.
// smem (floats): hs[16384] | Wt2[4096 float2 = 8192 floats] | Pf[4096]  = 112 KB
__global__ __launch_bounds__(256, 1)
void lstm_scan(const float* __restrict__ Whh_base, const int* __restrict__ xtok, int ysel) {
    extern __shared__ float sm[];
    float*  hs  = sm;                          // [k][b] 256*64
    float2* Wt2 = (float2*)(sm + 16384);       // [k*16 + g*4+u] duplicated pairs
    float*  Pf  = sm + 16384 + 8192;           // [kq*1024 + (g*4+u)*64 + b]

    const int tid = threadIdx.x;
    const int dir = blockIdx.x >> 6;
    const int u0  = (blockIdx.x & 63) << 2;
    float* Y = ysel ? d_H2 : d_H1;
    const float* Whh = Whh_base + (size_t)dir * (G4H * H_);

    for (int idx = tid; idx < 4096; idx += 256) {
        int k = idx >> 4, col = idx & 15;
        int g = col >> 2, u = col & 3;
        float w = Whh[(size_t)(g*256 + u0 + u) * 256 + k];
        Wt2[k*16 + col] = make_float2(w, w);
    }

    const int btile = tid & 15;
    const int g     = (tid >> 4) & 3;
    const int kq    = tid >> 6;
    const int eb    = tid & 63;
    const int eu    = tid >> 6;
    const int kh    = u0 + eu;

    d_hbuf[(size_t)(dir*2 + 0) * (H_*B_) + kh*64 + eb] = 0.f;
    float c_reg = 0.f;
    grid_barrier_dir(dir, 64);

    for (int s = 0; s < T_; s++) {
        const int t   = dir ? (T_-1-s) : s;
        const int cur = s & 1;
        const float4* hq4 = (const float4*)(d_hbuf + (size_t)(dir*2 + cur) * (H_*B_));
        float4* hs4 = (float4*)hs;

        // stage h: 4096 float4, 16 per thread, coalesced
#pragma unroll
        for (int i = 0; i < 16; i++)
            hs4[tid + (i << 8)] = __ldcg(&hq4[tid + (i << 8)]);

        // prefetch xp (coalesced, transposed layout) + token; consumed after compute
        const float* xpt = d_XP + (size_t)(dir*T_ + t) * (G4H*64);
        float xp0 = __ldcg(xpt + (size_t)(0*256 + kh)*64 + eb);
        float xp1 = __ldcg(xpt + (size_t)(1*256 + kh)*64 + eb);
        float xp2 = __ldcg(xpt + (size_t)(2*256 + kh)*64 + eb);
        float xp3 = __ldcg(xpt + (size_t)(3*256 + kh)*64 + eb);
        int   tok = __ldg(&xtok[t*64 + eb]);
        __syncthreads();

        unsigned long long acc[8];
#pragma unroll
        for (int i = 0; i < 8; i++) acc[i] = 0ULL;
        const int kbase = kq << 6;
#pragma unroll 8
        for (int kk = 0; kk < 64; kk++) {
            int k = kbase + kk;
            ulonglong2 hp = *(const ulonglong2*)&hs[(k << 6) + (btile << 2)];
            ulonglong2 wa = *(const ulonglong2*)&Wt2[k*16 + (g << 2)];
            ulonglong2 wb = *(const ulonglong2*)&Wt2[k*16 + (g << 2) + 2];
            FMA2(acc[0], wa.x, hp.x); FMA2(acc[1], wa.x, hp.y);
            FMA2(acc[2], wa.y, hp.x); FMA2(acc[3], wa.y, hp.y);
            FMA2(acc[4], wb.x, hp.x); FMA2(acc[5], wb.x, hp.y);
            FMA2(acc[6], wb.y, hp.x); FMA2(acc[7], wb.y, hp.y);
        }
        float hold = hs[(kh << 6) + eb];
#pragma unroll
        for (int u = 0; u < 4; u++) {
            float2 p0 = u64_as_f2(acc[u*2 + 0]);
            float2 p1 = u64_as_f2(acc[u*2 + 1]);
            *(float4*)&Pf[kq*1024 + ((g << 2) + u)*64 + (btile << 2)] =
                make_float4(p0.x, p0.y, p1.x, p1.y);
        }
        __syncthreads();

        float s0 = Pf[eu*64+eb]      + Pf[1024 + eu*64+eb]      + Pf[2048 + eu*64+eb]      + Pf[3072 + eu*64+eb];
        float s1 = Pf[(4+eu)*64+eb]  + Pf[1024 + (4+eu)*64+eb]  + Pf[2048 + (4+eu)*64+eb]  + Pf[3072 + (4+eu)*64+eb];
        float s2 = Pf[(8+eu)*64+eb]  + Pf[1024 + (8+eu)*64+eb]  + Pf[2048 + (8+eu)*64+eb]  + Pf[3072 + (8+eu)*64+eb];
        float s3 = Pf[(12+eu)*64+eb] + Pf[1024 + (12+eu)*64+eb] + Pf[2048 + (12+eu)*64+eb] + Pf[3072 + (12+eu)*64+eb];

        float i_ = sigf(s0 + xp0);
        float f_ = sigf(s1 + xp1);
        float g_ = tanhf(s2 + xp2);
        float o_ = sigf(s3 + xp3);
        float cn = f_*c_reg + i_*g_;
        float hn = o_*tanhf(cn);

        bool m = (tok != 0);
        float hw = m ? hn : hold;
        c_reg    = m ? cn : c_reg;

        d_hbuf[(size_t)(dir*2 + (cur^1)) * (H_*B_) + kh*64 + eb] = hw;
        Y[((size_t)t*64 + eb)*512 + (dir << 8) + kh] = m ? hn : 0.f;

        grid_barrier_dir(dir, 64);
    }
}

__global__ void emissions_kernel(const float* __restrict__ w_lin, const float* __restrict__ b_lin) {
    int idx = blockIdx.x * 256 + threadIdx.x;
    if (idx >= T_*B_*NTAG) return;
    int row = idx / NTAG;
    int n   = idx - row * NTAG;
    const float4* hr = (const float4*)(d_H2 + (size_t)row * 512);
    const float4* wr = (const float4*)(w_lin + (size_t)n * 512);
    float acc = 0.f;
#pragma unroll 8
    for (int k = 0; k < 128; k++) {
        float4 h = hr[k]; float4 w = wr[k];
        acc += h.x*w.x + h.y*w.y + h.z*w.z + h.w*w.w;
    }
    d_EM[idx] = acc + b_lin[n];
}

// Output tags as FLOAT32 (harness output dtype is float32 — verified R5).
__global__ __launch_bounds__(64)
void viterbi_kernel(const int* __restrict__ x, const float* __restrict__ start,
                    const float* __restrict__ endt, const float* __restrict__ trans,
                    float* __restrict__ out) {
    const int b = blockIdx.x;
    const int tid = threadIdx.x;
    __shared__ float trans_s[NTAG*NTAG];
    __shared__ float score[NTAG];
    __shared__ unsigned char hist[T_-1][NTAG];

    for (int i = tid; i < NTAG*NTAG; i += 64) trans_s[i] = trans[i];
    if (tid < NTAG) score[tid] = start[tid] + d_EM[b*NTAG + tid];
    __syncthreads();

    for (int t = 1; t < T_; t++) {
        float nv = 0.f;
        if (tid < NTAG) {
            float em = d_EM[(t*64 + b)*NTAG + tid];
            float best = -3.402823466e38f;
            int a = 0;
#pragma unroll
            for (int p = 0; p < NTAG; p++) {
                float sv = score[p] + trans_s[p*NTAG + tid];
                if (sv > best) { best = sv; a = p; }
            }
            bool m = (x[t*64 + b] != 0);
            nv = m ? (best + em) : score[tid];
            hist[t-1][tid] = (unsigned char)(m ? a : tid);
        }
        __syncthreads();
        if (tid < NTAG) score[tid] = nv;
        __syncthreads();
    }

    if (tid == 0) {
        float best = -3.402823466e38f;
        int tag = 0;
        for (int n = 0; n < NTAG; n++) {
            float sv = score[n] + endt[n];
            if (sv > best) { best = sv; tag = n; }
        }
        for (int t = T_-1; t >= 1; t--) {
            out[t*64 + b] = (x[t*64 + b] != 0) ? (float)tag : 0.f;
            tag = hist[t-1][tag];
        }
        out[b] = (x[b] != 0) ? (float)tag : 0.f;
    }
}

extern "C" void kernel_launch(void* const* d_in, const int* in_sizes, int n_in,
                              void* d_out, int out_size) {
    const void* P[16];
    if (n_in >= 16 && in_sizes[0] == T_*B_ && in_sizes[2] == 30000*256) {
        for (int i = 0; i < 16; i++) P[i] = d_in[i];
    } else if (n_in >= 15 && in_sizes[0] == T_*B_ && in_sizes[1] == 30000*256) {
        P[0] = d_in[0]; P[1] = d_in[0];
        for (int i = 2; i < 16; i++) P[i] = d_in[i-1];
    } else {
        P[0]  = d_in[15]; P[1]  = d_in[7];  P[2]  = d_in[5];
        P[3]  = d_in[12]; P[4]  = d_in[10]; P[5]  = d_in[2];  P[6]  = d_in[0];
        P[7]  = d_in[13]; P[8]  = d_in[11]; P[9]  = d_in[3];  P[10] = d_in[1];
        P[11] = d_in[14]; P[12] = d_in[4];
        P[13] = d_in[8];  P[14] = d_in[6];  P[15] = d_in[9];
    }

    const int*   x      = (const int*)P[0];
    const float* embed  = (const float*)P[2];
    const float* w_ih0  = (const float*)P[3];
    const float* w_hh0  = (const float*)P[4];
    const float* b_ih0  = (const float*)P[5];
    const float* b_hh0  = (const float*)P[6];
    const float* w_ih1  = (const float*)P[7];
    const float* w_hh1  = (const float*)P[8];
    const float* b_ih1  = (const float*)P[9];
    const float* b_hh1  = (const float*)P[10];
    const float* w_lin  = (const float*)P[11];
    const float* b_lin  = (const float*)P[12];
    const float* startt = (const float*)P[13];
    const float* endt   = (const float*)P[14];
    const float* trans  = (const float*)P[15];
    float* out = (float*)d_out;

    const int SMEM_SCAN = 112 * 1024;
    cudaFuncSetAttribute(lstm_scan, cudaFuncAttributeMaxDynamicSharedMemorySize, SMEM_SCAN);

    embed_kernel<<<4096, 256>>>(x, embed);
    sgemm_bias<<<dim3(8, 128, 2), 256>>>(0, w_ih0, b_ih0, b_hh0, 256);
    lstm_scan<<<128, 256, SMEM_SCAN>>>(w_hh0, x, 0);
    sgemm_bias<<<dim3(8, 128, 2), 256>>>(1, w_ih1, b_ih1, b_hh1, 512);
    lstm_scan<<<128, 256, SMEM_SCAN>>>(w_hh1, x, 1);
    emissions_kernel<<<(T_*B_*NTAG + 255)/256, 256>>>(w_lin, b_lin);
    viterbi_kernel<<<64, 64>>>(x, startt, endt, trans, out);
}

// round 11
// speedup vs baseline: 2.2206x; 1.0164x over previous
#include <cuda_runtime.h>
#include <cuda_bf16.h>
#include <math.h>

#define T_   256
#define B_   64
#define H_   256
#define HID_ 512
#define NTAG 34
#define G4H  1024

__device__ float d_X0[T_*B_*256];
__device__ float d_H1[T_*B_*HID_];
__device__ float d_H2[T_*B_*HID_];
__device__ float d_XP[2u*T_*B_*G4H];   // [dir][t][gate n (1024)][b (64)]
__device__ float d_EM[T_*B_*NTAG];
__device__ float d_hbuf[2*2*H_*B_];    // [dir][pingpong][k][b]
__device__ volatile int g_flag[2][64*32];   // per-CTA arrive flags, 128B strided
__device__ volatile int g_rel[2][32];       // release flags

// packed dual fp32 FMA (exact fp32 per lane)
#define FMA2(d, a, b) asm("fma.rn.f32x2 %0, %1, %2, %0;" : "+l"(d) : "l"(a), "l"(b))

__device__ __forceinline__ float2 u64_as_f2(unsigned long long v) {
    float2 r; asm("mov.b64 {%0, %1}, %2;" : "=f"(r.x), "=f"(r.y) : "l"(v)); return r;
}

// Flag-array barrier: per-CTA arrive flags (no atomic contention), leader polls in parallel.
__device__ __forceinline__ void flag_barrier(int dir, int myid, int val) {
    __syncthreads();
    if (threadIdx.x == 0) { __threadfence(); g_flag[dir][myid*32] = val; }
    if (myid == 0) {
        if (threadIdx.x < 64) { while (g_flag[dir][threadIdx.x*32] < val) { } }
        __syncthreads();
        if (threadIdx.x == 0) g_rel[dir][0] = val;
    }
    if (threadIdx.x == 0) { while (g_rel[dir][0] < val) { } }
    __syncthreads();
}

__global__ void zero_flags() {
    int i = blockIdx.x * 256 + threadIdx.x;
    if (i < 64*32) { g_flag[0][i] = 0; g_flag[1][i] = 0; }
    if (i < 32)    { g_rel[0][i] = 0;  g_rel[1][i] = 0; }
}

__global__ void embed_kernel(const int* __restrict__ x, const float* __restrict__ embed) {
    size_t idx = (size_t)blockIdx.x * 256 + threadIdx.x;   // over T*B*64 float4
    int row = (int)(idx >> 6);
    int c   = (int)(idx & 63);
    int tok = x[row];
    ((float4*)d_X0)[idx] = ((const float4*)embed)[(size_t)tok * 64 + c];
}

// Transposed output: C[t][n][b] = A[m=t*64+b,:].W[n,:] + bi[n] + bh[n]
// Block 128m x 128n, 256 threads, microtile 4m x 16n, FMA2 inner.
__global__ __launch_bounds__(256, 2)
void sgemm_bias(int asel, const float* __restrict__ Wbase,
                const float* __restrict__ bi_base, const float* __restrict__ bh_base, int K) {
    const float* A = asel ? d_H1 : d_X0;
    const int z = blockIdx.z;
    const float* W  = Wbase + (size_t)z * 1024 * K;
    const float* bi = bi_base + (size_t)z * 1024;
    const float* bh = bh_base + (size_t)z * 1024;
    float* C = d_XP + (size_t)z * (T_*B_*G4H);

    __shared__ float2 As2[8][128];   // duplicated pairs [k][m], 8 KB
    __shared__ float  Bs[8][128];    // [k][n], 4 KB

    const int tid = threadIdx.x;
    const int m0 = blockIdx.y * 128;
    const int n0 = blockIdx.x * 128;

    const int lm  = tid >> 1;            // 0..127
    const int lk4 = (tid & 1) * 4;       // 0 or 4
    const float* aptr = A + (size_t)(m0 + lm) * K + lk4;
    const float* wptr = W + (size_t)(n0 + lm) * K + lk4;

    const int my = tid >> 3;             // 0..31, m = my*4 + i
    const int tx = tid & 7;              // n groups: {0,32,64,96} + tx*4

    unsigned long long acc[4][8];        // [i m][n-pair p]
#pragma unroll
    for (int i = 0; i < 4; i++)
#pragma unroll
        for (int p = 0; p < 8; p++) acc[i][p] = 0ULL;

    for (int kt = 0; kt < (K >> 3); kt++) {
        float4 av = *(const float4*)aptr;
        float4 wv = *(const float4*)wptr;
        aptr += 8; wptr += 8;
        __syncthreads();
        As2[lk4+0][lm] = make_float2(av.x, av.x);
        As2[lk4+1][lm] = make_float2(av.y, av.y);
        As2[lk4+2][lm] = make_float2(av.z, av.z);
        As2[lk4+3][lm] = make_float2(av.w, av.w);
        Bs[lk4+0][lm] = wv.x; Bs[lk4+1][lm] = wv.y; Bs[lk4+2][lm] = wv.z; Bs[lk4+3][lm] = wv.w;
        __syncthreads();
#pragma unroll
        for (int kk = 0; kk < 8; kk++) {
            ulonglong2 a01 = *(const ulonglong2*)&As2[kk][my*4];
            ulonglong2 a23 = *(const ulonglong2*)&As2[kk][my*4 + 2];
            unsigned long long aD[4] = {a01.x, a01.y, a23.x, a23.y};
            ulonglong2 b0 = *(const ulonglong2*)&Bs[kk][tx*4];
            ulonglong2 b1 = *(const ulonglong2*)&Bs[kk][32 + tx*4];
            ulonglong2 b2 = *(const ulonglong2*)&Bs[kk][64 + tx*4];
            ulonglong2 b3 = *(const ulonglong2*)&Bs[kk][96 + tx*4];
#pragma unroll
            for (int i = 0; i < 4; i++) {
                FMA2(acc[i][0], aD[i], b0.x); FMA2(acc[i][1], aD[i], b0.y);
                FMA2(acc[i][2], aD[i], b1.x); FMA2(acc[i][3], aD[i], b1.y);
                FMA2(acc[i][4], aD[i], b2.x); FMA2(acc[i][5], aD[i], b2.y);
                FMA2(acc[i][6], aD[i], b3.x); FMA2(acc[i][7], aD[i], b3.y);
            }
        }
    }
    // epilogue: m = m0 + my*4 + i -> t = m0/64 + (my>>4), b = (my&15)*4 + i
    const int tt  = (m0 >> 6) + (my >> 4);
    const int b0e = (my & 15) * 4;
    float* Ct = C + (size_t)tt * (G4H*64);
#pragma unroll
    for (int p = 0; p < 8; p++) {
        int n = n0 + (p >> 1)*32 + tx*4 + (p & 1)*2;
        float bias0 = bi[n] + bh[n];
        float bias1 = bi[n+1] + bh[n+1];
        float2 t0 = u64_as_f2(acc[0][p]);
        float2 t1 = u64_as_f2(acc[1][p]);
        float2 t2 = u64_as_f2(acc[2][p]);
        float2 t3 = u64_as_f2(acc[3][p]);
        *(float4*)(Ct + (size_t)n*64 + b0e) =
            make_float4(t0.x+bias0, t1.x+bias0, t2.x+bias0, t3.x+bias0);
        *(float4*)(Ct + (size_t)(n+1)*64 + b0e) =
            make_float4(t0.y+bias1, t1.y+bias1, t2.y+bias1, t3.y+bias1);
    }
}

__device__ __forceinline__ float sigf(float v) { return 1.f / (1.f + expf(-v)); }

// Persistent scan: 128 CTAs, dir = bx>>6, 4 hidden units per CTA, flag barrier per step.
// smem (floats): hs[16384] | Wt2[4096 float2 = 8192 floats] | Pf[4096]  = 112 KB
__global__ __launch_bounds__(256, 1)
void lstm_scan(const float* __restrict__ Whh_base, const int* __restrict__ xtok, int ysel) {
    extern __shared__ float sm[];
    float*  hs  = sm;                          // [k][b] 256*64
    float2* Wt2 = (float2*)(sm + 16384);       // [k*16 + g*4+u] duplicated pairs
    float*  Pf  = sm + 16384 + 8192;           // [kq*1024 + (g*4+u)*64 + b]

    const int tid  = threadIdx.x;
    const int dir  = blockIdx.x >> 6;
    const int myid = blockIdx.x & 63;
    const int u0   = myid << 2;
    float* Y = ysel ? d_H2 : d_H1;
    const float* Whh = Whh_base + (size_t)dir * (G4H * H_);

    for (int idx = tid; idx < 4096; idx += 256) {
        int k = idx >> 4, col = idx & 15;
        int g = col >> 2, u = col & 3;
        float w = Whh[(size_t)(g*256 + u0 + u) * 256 + k];
        Wt2[k*16 + col] = make_float2(w, w);
    }

    const int btile = tid & 15;
    const int g     = (tid >> 4) & 3;
    const int kq    = tid >> 6;
    const int eb    = tid & 63;
    const int eu    = tid >> 6;
    const int kh    = u0 + eu;

    d_hbuf[(size_t)(dir*2 + 0) * (H_*B_) + kh*64 + eb] = 0.f;
    float c_reg = 0.f;
    flag_barrier(dir, myid, 1);

    for (int s = 0; s < T_; s++) {
        const int t   = dir ? (T_-1-s) : s;
        const int cur = s & 1;
        const float4* hq4 = (const float4*)(d_hbuf + (size_t)(dir*2 + cur) * (H_*B_));
        float4* hs4 = (float4*)hs;

#pragma unroll
        for (int i = 0; i < 16; i++)
            hs4[tid + (i << 8)] = __ldcg(&hq4[tid + (i << 8)]);

        const float* xpt = d_XP + (size_t)(dir*T_ + t) * (G4H*64);
        float xp0 = __ldcg(xpt + (size_t)(0*256 + kh)*64 + eb);
        float xp1 = __ldcg(xpt + (size_t)(1*256 + kh)*64 + eb);
        float xp2 = __ldcg(xpt + (size_t)(2*256 + kh)*64 + eb);
        float xp3 = __ldcg(xpt + (size_t)(3*256 + kh)*64 + eb);
        int   tok = __ldg(&xtok[t*64 + eb]);
        __syncthreads();

        unsigned long long acc[8];
#pragma unroll
        for (int i = 0; i < 8; i++) acc[i] = 0ULL;
        const int kbase = kq << 6;
#pragma unroll 8
        for (int kk = 0; kk < 64; kk++) {
            int k = kbase + kk;
            ulonglong2 hp = *(const ulonglong2*)&hs[(k << 6) + (btile << 2)];
            ulonglong2 wa = *(const ulonglong2*)&Wt2[k*16 + (g << 2)];
            ulonglong2 wb = *(const ulonglong2*)&Wt2[k*16 + (g << 2) + 2];
            FMA2(acc[0], wa.x, hp.x); FMA2(acc[1], wa.x, hp.y);
            FMA2(acc[2], wa.y, hp.x); FMA2(acc[3], wa.y, hp.y);
            FMA2(acc[4], wb.x, hp.x); FMA2(acc[5], wb.x, hp.y);
            FMA2(acc[6], wb.y, hp.x); FMA2(acc[7], wb.y, hp.y);
        }
        float hold = hs[(kh << 6) + eb];
#pragma unroll
        for (int u = 0; u < 4; u++) {
            float2 p0 = u64_as_f2(acc[u*2 + 0]);
            float2 p1 = u64_as_f2(acc[u*2 + 1]);
            *(float4*)&Pf[kq*1024 + ((g << 2) + u)*64 + (btile << 2)] =
                make_float4(p0.x, p0.y, p1.x, p1.y);
        }
        __syncthreads();

        float s0 = Pf[eu*64+eb]      + Pf[1024 + eu*64+eb]      + Pf[2048 + eu*64+eb]      + Pf[3072 + eu*64+eb];
        float s1 = Pf[(4+eu)*64+eb]  + Pf[1024 + (4+eu)*64+eb]  + Pf[2048 + (4+eu)*64+eb]  + Pf[3072 + (4+eu)*64+eb];
        float s2 = Pf[(8+eu)*64+eb]  + Pf[1024 + (8+eu)*64+eb]  + Pf[2048 + (8+eu)*64+eb]  + Pf[3072 + (8+eu)*64+eb];
        float s3 = Pf[(12+eu)*64+eb] + Pf[1024 + (12+eu)*64+eb] + Pf[2048 + (12+eu)*64+eb] + Pf[3072 + (12+eu)*64+eb];

        float i_ = sigf(s0 + xp0);
        float f_ = sigf(s1 + xp1);
        float g_ = tanhf(s2 + xp2);
        float o_ = sigf(s3 + xp3);
        float cn = f_*c_reg + i_*g_;
        float hn = o_*tanhf(cn);

        bool m = (tok != 0);
        float hw = m ? hn : hold;
        c_reg    = m ? cn : c_reg;

        d_hbuf[(size_t)(dir*2 + (cur^1)) * (H_*B_) + kh*64 + eb] = hw;
        Y[((size_t)t*64 + eb)*512 + (dir << 8) + kh] = m ? hn : 0.f;

        flag_barrier(dir, myid, s + 2);
    }
}

__global__ void emissions_kernel(const float* __restrict__ w_lin, const float* __restrict__ b_lin) {
    int idx = blockIdx.x * 256 + threadIdx.x;
    if (idx >= T_*B_*NTAG) return;
    int row = idx / NTAG;
    int n   = idx - row * NTAG;
    const float4* hr = (const float4*)(d_H2 + (size_t)row * 512);
    const float4* wr = (const float4*)(w_lin + (size_t)n * 512);
    float acc = 0.f;
#pragma unroll 8
    for (int k = 0; k < 128; k++) {
        float4 h = hr[k]; float4 w = wr[k];
        acc += h.x*w.x + h.y*w.y + h.z*w.z + h.w*w.w;
    }
    d_EM[idx] = acc + b_lin[n];
}

// Output tags as FLOAT32 (harness output dtype is float32 — verified R5).
__global__ __launch_bounds__(64)
void viterbi_kernel(const int* __restrict__ x, const float* __restrict__ start,
                    const float* __restrict__ endt, const float* __restrict__ trans,
                    float* __restrict__ out) {
    const int b = blockIdx.x;
    const int tid = threadIdx.x;
    __shared__ float trans_s[NTAG*NTAG];
    __shared__ float score[NTAG];
    __shared__ unsigned char hist[T_-1][NTAG];

    for (int i = tid; i < NTAG*NTAG; i += 64) trans_s[i] = trans[i];
    if (tid < NTAG) score[tid] = start[tid] + d_EM[b*NTAG + tid];
    __syncthreads();

    for (int t = 1; t < T_; t++) {
        float nv = 0.f;
        if (tid < NTAG) {
            float em = d_EM[(t*64 + b)*NTAG + tid];
            float best = -3.402823466e38f;
            int a = 0;
#pragma unroll
            for (int p = 0; p < NTAG; p++) {
                float sv = score[p] + trans_s[p*NTAG + tid];
                if (sv > best) { best = sv; a = p; }
            }
            bool m = (x[t*64 + b] != 0);
            nv = m ? (best + em) : score[tid];
            hist[t-1][tid] = (unsigned char)(m ? a : tid);
        }
        __syncthreads();
        if (tid < NTAG) score[tid] = nv;
        __syncthreads();
    }

    if (tid == 0) {
        float best = -3.402823466e38f;
        int tag = 0;
        for (int n = 0; n < NTAG; n++) {
            float sv = score[n] + endt[n];
            if (sv > best) { best = sv; tag = n; }
        }
        for (int t = T_-1; t >= 1; t--) {
            out[t*64 + b] = (x[t*64 + b] != 0) ? (float)tag : 0.f;
            tag = hist[t-1][tag];
        }
        out[b] = (x[b] != 0) ? (float)tag : 0.f;
    }
}

extern "C" void kernel_launch(void* const* d_in, const int* in_sizes, int n_in,
                              void* d_out, int out_size) {
    const void* P[16];
    if (n_in >= 16 && in_sizes[0] == T_*B_ && in_sizes[2] == 30000*256) {
        for (int i = 0; i < 16; i++) P[i] = d_in[i];
    } else if (n_in >= 15 && in_sizes[0] == T_*B_ && in_sizes[1] == 30000*256) {
        P[0] = d_in[0]; P[1] = d_in[0];
        for (int i = 2; i < 16; i++) P[i] = d_in[i-1];
    } else {
        P[0]  = d_in[15]; P[1]  = d_in[7];  P[2]  = d_in[5];
        P[3]  = d_in[12]; P[4]  = d_in[10]; P[5]  = d_in[2];  P[6]  = d_in[0];
        P[7]  = d_in[13]; P[8]  = d_in[11]; P[9]  = d_in[3];  P[10] = d_in[1];
        P[11] = d_in[14]; P[12] = d_in[4];
        P[13] = d_in[8];  P[14] = d_in[6];  P[15] = d_in[9];
    }

    const int*   x      = (const int*)P[0];
    const float* embed  = (const float*)P[2];
    const float* w_ih0  = (const float*)P[3];
    const float* w_hh0  = (const float*)P[4];
    const float* b_ih0  = (const float*)P[5];
    const float* b_hh0  = (const float*)P[6];
    const float* w_ih1  = (const float*)P[7];
    const float* w_hh1  = (const float*)P[8];
    const float* b_ih1  = (const float*)P[9];
    const float* b_hh1  = (const float*)P[10];
    const float* w_lin  = (const float*)P[11];
    const float* b_lin  = (const float*)P[12];
    const float* startt = (const float*)P[13];
    const float* endt   = (const float*)P[14];
    const float* trans  = (const float*)P[15];
    float* out = (float*)d_out;

    const int SMEM_SCAN = 112 * 1024;
    cudaFuncSetAttribute(lstm_scan, cudaFuncAttributeMaxDynamicSharedMemorySize, SMEM_SCAN);

    embed_kernel<<<4096, 256>>>(x, embed);
    sgemm_bias<<<dim3(8, 128, 2), 256>>>(0, w_ih0, b_ih0, b_hh0, 256);
    lstm_scan<<<128, 256, SMEM_SCAN>>>(w_hh0, x, 0);
    zero_flags<<<8, 256>>>();
    sgemm_bias<<<dim3(8, 128, 2), 256>>>(1, w_ih1, b_ih1, b_hh1, 512);
    lstm_scan<<<128, 256, SMEM_SCAN>>>(w_hh1, x, 1);
    zero_flags<<<8, 256>>>();
    emissions_kernel<<<(T_*B_*NTAG + 255)/256, 256>>>(w_lin, b_lin);
    viterbi_kernel<<<64, 64>>>(x, startt, endt, trans, out);
}